// round 4
// baseline (speedup 1.0000x reference)
#include <cuda_runtime.h>
#include <math.h>
#include <stdint.h>

// ---------------- problem constants ----------------
#define NN 50000         // nodes
#define NE 600000        // edges
#define HD 128           // hidden
#define NG 64            // graphs
#define K3 384           // 3*H
#define NLAYERS 2
#define NSTEPS 2

// ---------------- device scratch (no allocs allowed) ----------------
__device__ float d_h[(size_t)NN * HD];
__device__ float d_S[(size_t)NN * K3];
__device__ float d_a[(size_t)NN * HD];
__device__ float d_gi[(size_t)NN * K3];
__device__ float d_gh[(size_t)NN * K3];
__device__ float d_deg[(size_t)NN * 3];
__device__ int   d_cnt[NN];
__device__ int   d_rowptr[NN + 1];
__device__ int   d_cursor[NN];
__device__ int   d_edges[NE];
__device__ int   d_goff[NG + 1];
__device__ float d_wcatT[2 * HD * K3];   // per layer: [128 out][384 k]
__device__ float d_agg[NG * K3];

// ---------------- small kernels ----------------

// WcatT[l][o][t*128+h] = Wl[l][t][h][o]
__global__ void transpose_wl_kernel(const float* __restrict__ Wl, float* __restrict__ wcatT) {
    int idx = blockIdx.x * blockDim.x + threadIdx.x;
    if (idx >= 2 * 3 * 128 * 128) return;
    int o  = idx & 127;
    int hh = (idx >> 7) & 127;
    int lt = idx >> 14;
    int t  = lt % 3;
    int l  = lt / 3;
    wcatT[(size_t)l * HD * K3 + (size_t)o * K3 + t * 128 + hh] = Wl[idx];
}

__global__ void count_edges_kernel(const int* __restrict__ dst, int* __restrict__ cnt) {
    int e = blockIdx.x * blockDim.x + threadIdx.x;
    if (e < NE) atomicAdd(&cnt[dst[e]], 1);
}

// single-block inclusive scan with carry -> rowptr (exclusive, +1 shifted) and cursor
__global__ void scan_counts_kernel(const int* __restrict__ cnt, int* __restrict__ rowptr,
                                   int* __restrict__ cursor, int n) {
    __shared__ int sh[1024];
    __shared__ int carry;
    int tid = threadIdx.x;
    if (tid == 0) { carry = 0; rowptr[0] = 0; }
    __syncthreads();
    for (int base = 0; base < n; base += 1024) {
        int i = base + tid;
        int v = (i < n) ? cnt[i] : 0;
        sh[tid] = v;
        __syncthreads();
        for (int off = 1; off < 1024; off <<= 1) {
            int t = (tid >= off) ? sh[tid - off] : 0;
            __syncthreads();
            sh[tid] += t;
            __syncthreads();
        }
        int incl = sh[tid];
        int c = carry;
        if (i < n) {
            rowptr[i + 1] = c + incl;
            cursor[i]     = c + incl - v;   // exclusive prefix
        }
        __syncthreads();
        if (tid == 1023) carry = c + sh[1023];
        __syncthreads();
    }
}

__global__ void place_edges_kernel(const int* __restrict__ src, const int* __restrict__ dst,
                                   const int* __restrict__ etype, int* __restrict__ cursor,
                                   int* __restrict__ edges) {
    int e = blockIdx.x * blockDim.x + threadIdx.x;
    if (e >= NE) return;
    int d = dst[e];
    int pos = atomicAdd(&cursor[d], 1);
    edges[pos] = src[e] | (etype[e] << 24);
}

// graph_id is sorted: goff[g] = lower_bound(graph_id, g)
__global__ void goff_kernel(const int* __restrict__ graph_id, int* __restrict__ goff) {
    int g = threadIdx.x;
    if (g > NG) return;
    if (g == NG) { goff[NG] = NN; return; }
    int lo = 0, hi = NN;
    while (lo < hi) {
        int mid = (lo + hi) >> 1;
        if (graph_id[mid] < g) lo = mid + 1; else hi = mid;
    }
    goff[g] = lo;
}

__global__ void embed_kernel(const int* __restrict__ text_idx, const float* __restrict__ emb,
                             float* __restrict__ h) {
    int idx = blockIdx.x * blockDim.x + threadIdx.x;
    if (idx >= NN * HD) return;
    int n = idx >> 7, c = idx & 127;
    h[idx] = emb[(size_t)text_idx[n] * HD + c];
}

// segment mean by graph (contiguous node ranges); writes agg[g][slot*128 + c]
__global__ void mean_kernel(const float* __restrict__ h, const int* __restrict__ goff,
                            float* __restrict__ agg, int slot) {
    int g = blockIdx.x;
    int c = threadIdx.x; // 128
    int s = goff[g], e = goff[g + 1];
    float a0 = 0.f, a1 = 0.f, a2 = 0.f, a3 = 0.f;
    int r = s;
    for (; r + 4 <= e; r += 4) {
        a0 += h[(size_t)(r + 0) * HD + c];
        a1 += h[(size_t)(r + 1) * HD + c];
        a2 += h[(size_t)(r + 2) * HD + c];
        a3 += h[(size_t)(r + 3) * HD + c];
    }
    for (; r < e; ++r) a0 += h[(size_t)r * HD + c];
    float acc = (a0 + a1) + (a2 + a3);
    float cntf = (float)((e - s) > 0 ? (e - s) : 1);
    agg[g * K3 + slot * HD + c] = acc / cntf;
}

__device__ __forceinline__ void f4add(float4& a, const float4& b) {
    a.x += b.x; a.y += b.y; a.z += b.z; a.w += b.w;
}

// one warp per dst node: per-etype raw-feature sums -> S[n][t*128 + col], deg counts
__global__ void aggregate_kernel(const float* __restrict__ h, const int* __restrict__ rowptr,
                                 const int* __restrict__ edges, float* __restrict__ S,
                                 float* __restrict__ deg) {
    int warp = (blockIdx.x * blockDim.x + threadIdx.x) >> 5;
    int lane = threadIdx.x & 31;
    if (warp >= NN) return;
    int s = rowptr[warp], e = rowptr[warp + 1];
    float4 a0 = {0,0,0,0}, a1 = {0,0,0,0}, a2 = {0,0,0,0};
    int c0 = 0, c1 = 0, c2 = 0;
    const float4* h4 = (const float4*)h;
    for (int i = s; i < e; ++i) {
        int p = edges[i];
        int srcn = p & 0xFFFFFF;
        int t = p >> 24;
        float4 v = h4[(size_t)srcn * 32 + lane];
        if (t == 0)      { f4add(a0, v); c0++; }
        else if (t == 1) { f4add(a1, v); c1++; }
        else             { f4add(a2, v); c2++; }
    }
    float4* S4 = (float4*)S;
    size_t base = (size_t)warp * 96;
    S4[base + lane]      = a0;
    S4[base + 32 + lane] = a1;
    S4[base + 64 + lane] = a2;
    if (lane == 0) {
        deg[(size_t)warp * 3 + 0] = (float)c0;
        deg[(size_t)warp * 3 + 1] = (float)c1;
        deg[(size_t)warp * 3 + 2] = (float)c2;
    }
}

// ---------------- SGEMM: C[m][j] = sum_k A[m][k] * B[j][k]  (C = A·B^T) ----------------
// A: [M x K] row-major (K mult of 16), B: [J x K] row-major (J mult of 128)
// mode 0: none; mode 1: +bias[j]; mode 2: +deg[m][t]*bl3[t*128 + j]  (J==128 only)
__global__ __launch_bounds__(256) void sgemm_abt_kernel(
    const float* __restrict__ A, const float* __restrict__ B, float* __restrict__ C,
    int M, int K, int J, int mode,
    const float* __restrict__ bias, const float* __restrict__ deg,
    const float* __restrict__ bl3)
{
    __shared__ float As[2][16][128];
    __shared__ float Bs[2][16][128];

    const int tid = threadIdx.x;
    const int tx = tid & 15;
    const int ty = tid >> 4;
    const int m0 = blockIdx.x * 128;
    const int j0 = blockIdx.y * 128;

    float acc[8][8];
#pragma unroll
    for (int i = 0; i < 8; ++i)
#pragma unroll
        for (int j = 0; j < 8; ++j) acc[i][j] = 0.f;

    float4 stA[2], stB[2];
    const int numT = K >> 4;

    auto LOAD = [&](int t) {
        int k0 = t * 16;
#pragma unroll
        for (int u = 0; u < 2; ++u) {
            int f = tid + u * 256;
            int m = f >> 2, kq = f & 3;
            int gm = m0 + m;
            if (gm < M) stA[u] = *(const float4*)(A + (size_t)gm * K + k0 + kq * 4);
            else        stA[u] = make_float4(0.f, 0.f, 0.f, 0.f);
            stB[u] = *(const float4*)(B + (size_t)(j0 + m) * K + k0 + kq * 4);
        }
    };
    auto STORE = [&](int buf) {
#pragma unroll
        for (int u = 0; u < 2; ++u) {
            int f = tid + u * 256;
            int m = f >> 2, kq = f & 3;
            As[buf][kq * 4 + 0][m] = stA[u].x;
            As[buf][kq * 4 + 1][m] = stA[u].y;
            As[buf][kq * 4 + 2][m] = stA[u].z;
            As[buf][kq * 4 + 3][m] = stA[u].w;
            Bs[buf][kq * 4 + 0][m] = stB[u].x;
            Bs[buf][kq * 4 + 1][m] = stB[u].y;
            Bs[buf][kq * 4 + 2][m] = stB[u].z;
            Bs[buf][kq * 4 + 3][m] = stB[u].w;
        }
    };
    auto COMP = [&](int buf) {
#pragma unroll
        for (int kk = 0; kk < 16; ++kk) {
            float4 ra0 = *(const float4*)&As[buf][kk][ty * 4];
            float4 ra1 = *(const float4*)&As[buf][kk][64 + ty * 4];
            float4 rb0 = *(const float4*)&Bs[buf][kk][tx * 4];
            float4 rb1 = *(const float4*)&Bs[buf][kk][64 + tx * 4];
            float ra[8] = {ra0.x, ra0.y, ra0.z, ra0.w, ra1.x, ra1.y, ra1.z, ra1.w};
            float rb[8] = {rb0.x, rb0.y, rb0.z, rb0.w, rb1.x, rb1.y, rb1.z, rb1.w};
#pragma unroll
            for (int i = 0; i < 8; ++i)
#pragma unroll
                for (int j = 0; j < 8; ++j) acc[i][j] += ra[i] * rb[j];
        }
    };

    LOAD(0); STORE(0); __syncthreads();
    for (int t = 0; t < numT; ++t) {
        int cur = t & 1;
        if (t + 1 < numT) LOAD(t + 1);
        COMP(cur);
        if (t + 1 < numT) STORE(cur ^ 1);
        __syncthreads();
    }

    // epilogue
#pragma unroll
    for (int i = 0; i < 8; ++i) {
        int gm = m0 + ((i < 4) ? (ty * 4 + i) : (60 + ty * 4 + i));
        if (gm >= M) continue;
        float d0 = 0.f, d1 = 0.f, d2 = 0.f;
        if (mode == 2) {
            d0 = deg[(size_t)gm * 3 + 0];
            d1 = deg[(size_t)gm * 3 + 1];
            d2 = deg[(size_t)gm * 3 + 2];
        }
        float outv[8];
#pragma unroll
        for (int j = 0; j < 8; ++j) {
            int c = (j < 4) ? (tx * 4 + j) : (60 + tx * 4 + j);
            float v = acc[i][j];
            if (mode == 1)      v += bias[j0 + c];
            else if (mode == 2) v += d0 * bl3[c] + d1 * bl3[128 + c] + d2 * bl3[256 + c];
            outv[j] = v;
        }
        float4* cp = (float4*)(C + (size_t)gm * J + j0);
        cp[tx]      = make_float4(outv[0], outv[1], outv[2], outv[3]);
        cp[16 + tx] = make_float4(outv[4], outv[5], outv[6], outv[7]);
    }
}

// ---------------- GRU gates (in-place h update) ----------------
__global__ void gru_gates_kernel(const float* __restrict__ gi, const float* __restrict__ gh,
                                 float* __restrict__ h) {
    int idx = blockIdx.x * blockDim.x + threadIdx.x;
    if (idx >= NN * HD) return;
    int n = idx >> 7, c = idx & 127;
    size_t b = (size_t)n * K3;
    float ir = gi[b + c],       hr = gh[b + c];
    float iz = gi[b + 128 + c], hz = gh[b + 128 + c];
    float in_ = gi[b + 256 + c], hn = gh[b + 256 + c];
    float r = 1.f / (1.f + expf(-(ir + hr)));
    float z = 1.f / (1.f + expf(-(iz + hz)));
    float nc = tanhf(in_ + r * hn);
    h[idx] = (1.f - z) * nc + z * h[idx];
}

// ---------------- head: x = relu(agg@W1+b1); res = x@W2+b2; emit [res | agg] ----------------
__global__ void head_kernel(const float* __restrict__ agg, const float* __restrict__ W1,
                            const float* __restrict__ b1, const float* __restrict__ W2,
                            const float* __restrict__ b2, float* __restrict__ out,
                            int out_size) {
    int g = blockIdx.x;
    int o = threadIdx.x; // 128
    __shared__ float sa[K3];
    __shared__ float sx[HD];
    for (int k = o; k < K3; k += HD) sa[k] = agg[g * K3 + k];
    __syncthreads();
    float acc = b1[o];
    for (int k = 0; k < K3; ++k) acc += sa[k] * W1[k * HD + o];
    acc = fmaxf(acc, 0.f);
    sx[o] = acc * W2[o];
    __syncthreads();
    for (int st = 64; st > 0; st >>= 1) {
        if (o < st) sx[o] += sx[o + st];
        __syncthreads();
    }
    if (o == 0 && g < out_size) out[g] = sx[0] + b2[0];
    for (int k = o; k < K3; k += HD) {
        int oi = NG + g * K3 + k;
        if (oi < out_size) out[oi] = sa[k];
    }
}

// ---------------- host launch ----------------
extern "C" void kernel_launch(void* const* d_in, const int* in_sizes, int n_in,
                              void* d_out, int out_size) {
    const int*   text_idx = (const int*)d_in[0];
    const int*   src      = (const int*)d_in[1];
    const int*   dst      = (const int*)d_in[2];
    const int*   etype    = (const int*)d_in[3];
    const int*   graph_id = (const int*)d_in[4];
    const float* emb      = (const float*)d_in[5];
    const float* Wl       = (const float*)d_in[6];
    const float* bl       = (const float*)d_in[7];
    const float* W_ih     = (const float*)d_in[8];
    const float* W_hh     = (const float*)d_in[9];
    const float* b_ih     = (const float*)d_in[10];
    const float* b_hh     = (const float*)d_in[11];
    const float* W1       = (const float*)d_in[12];
    const float* b1       = (const float*)d_in[13];
    const float* W2       = (const float*)d_in[14];
    const float* b2       = (const float*)d_in[15];
    float* out = (float*)d_out;

    float *h, *S, *a, *gi, *gh, *deg, *wcatT, *agg;
    int *cnt, *rowptr, *cursor, *edges, *goff;
    cudaGetSymbolAddress((void**)&h,      d_h);
    cudaGetSymbolAddress((void**)&S,      d_S);
    cudaGetSymbolAddress((void**)&a,      d_a);
    cudaGetSymbolAddress((void**)&gi,     d_gi);
    cudaGetSymbolAddress((void**)&gh,     d_gh);
    cudaGetSymbolAddress((void**)&deg,    d_deg);
    cudaGetSymbolAddress((void**)&wcatT,  d_wcatT);
    cudaGetSymbolAddress((void**)&agg,    d_agg);
    cudaGetSymbolAddress((void**)&cnt,    d_cnt);
    cudaGetSymbolAddress((void**)&rowptr, d_rowptr);
    cudaGetSymbolAddress((void**)&cursor, d_cursor);
    cudaGetSymbolAddress((void**)&edges,  d_edges);
    cudaGetSymbolAddress((void**)&goff,   d_goff);

    // one-time (per launch) graph structure + weight transpose
    transpose_wl_kernel<<<(2 * 3 * 128 * 128 + 255) / 256, 256>>>(Wl, wcatT);
    cudaMemsetAsync(cnt, 0, NN * sizeof(int));
    count_edges_kernel<<<(NE + 255) / 256, 256>>>(dst, cnt);
    scan_counts_kernel<<<1, 1024>>>(cnt, rowptr, cursor, NN);
    place_edges_kernel<<<(NE + 255) / 256, 256>>>(src, dst, etype, cursor, edges);
    goff_kernel<<<1, NG + 1>>>(graph_id, goff);

    embed_kernel<<<(NN * HD + 255) / 256, 256>>>(text_idx, emb, h);
    mean_kernel<<<NG, HD>>>(h, goff, agg, 0);

    const dim3 g128((NN + 127) / 128, 1);
    const dim3 g384((NN + 127) / 128, 3);

    for (int l = 0; l < NLAYERS; ++l) {
        for (int s = 0; s < NSTEPS; ++s) {
            aggregate_kernel<<<(NN * 32 + 255) / 256, 256>>>(h, rowptr, edges, S, deg);
            // a = S @ WcatT^T + deg-weighted etype bias
            sgemm_abt_kernel<<<g128, 256>>>(S, wcatT + (size_t)l * HD * K3, a,
                                            NN, K3, HD, 2, nullptr, deg, bl + l * K3);
            // gi = a @ W_ih^T + b_ih
            sgemm_abt_kernel<<<g384, 256>>>(a, W_ih + (size_t)l * K3 * HD, gi,
                                            NN, HD, K3, 1, b_ih + l * K3, nullptr, nullptr);
            // gh = h @ W_hh^T + b_hh
            sgemm_abt_kernel<<<g384, 256>>>(h, W_hh + (size_t)l * K3 * HD, gh,
                                            NN, HD, K3, 1, b_hh + l * K3, nullptr, nullptr);
            gru_gates_kernel<<<(NN * HD + 255) / 256, 256>>>(gi, gh, h);
        }
        mean_kernel<<<NG, HD>>>(h, goff, agg, l + 1);
    }

    head_kernel<<<NG, HD>>>(agg, W1, b1, W2, b2, out, out_size);
}

// round 5
// speedup vs baseline: 1.7306x; 1.7306x over previous
#include <cuda_runtime.h>
#include <math.h>
#include <stdint.h>

// ---------------- problem constants ----------------
#define NN 50000         // nodes
#define NE 600000        // edges
#define HD 128           // hidden
#define NG 64            // graphs
#define K3 384           // 3*H
#define NLAYERS 2
#define NSTEPS 2

// ---------------- device scratch (no allocs allowed) ----------------
__device__ float d_h[(size_t)NN * HD];
__device__ float d_S[(size_t)NN * K3];
__device__ float d_a[(size_t)NN * HD];
__device__ float d_gi[(size_t)NN * K3];
__device__ float d_gh[(size_t)NN * K3];
__device__ float d_deg[(size_t)NN * 3];
__device__ int   d_cnt[NN];
__device__ int   d_rowptr[NN + 1];
__device__ int   d_cursor[NN];
__device__ int   d_edges[NE];
__device__ int   d_goff[NG + 1];
__device__ float d_wcatT[2 * HD * K3];   // per layer: [128 out][384 k]
__device__ float d_agg[NG * K3];

// ---------------- small kernels ----------------

// WcatT[l][o][t*128+h] = Wl[l][t][h][o]
__global__ void transpose_wl_kernel(const float* __restrict__ Wl, float* __restrict__ wcatT) {
    int idx = blockIdx.x * blockDim.x + threadIdx.x;
    if (idx >= 2 * 3 * 128 * 128) return;
    int o  = idx & 127;
    int hh = (idx >> 7) & 127;
    int lt = idx >> 14;
    int t  = lt % 3;
    int l  = lt / 3;
    wcatT[(size_t)l * HD * K3 + (size_t)o * K3 + t * 128 + hh] = Wl[idx];
}

__global__ void count_edges_kernel(const int* __restrict__ dst, int* __restrict__ cnt) {
    int e = blockIdx.x * blockDim.x + threadIdx.x;
    if (e < NE) atomicAdd(&cnt[dst[e]], 1);
}

// single-block inclusive scan with carry -> rowptr (exclusive, +1 shifted) and cursor
__global__ void scan_counts_kernel(const int* __restrict__ cnt, int* __restrict__ rowptr,
                                   int* __restrict__ cursor, int n) {
    __shared__ int sh[1024];
    __shared__ int carry;
    int tid = threadIdx.x;
    if (tid == 0) { carry = 0; rowptr[0] = 0; }
    __syncthreads();
    for (int base = 0; base < n; base += 1024) {
        int i = base + tid;
        int v = (i < n) ? cnt[i] : 0;
        sh[tid] = v;
        __syncthreads();
        for (int off = 1; off < 1024; off <<= 1) {
            int t = (tid >= off) ? sh[tid - off] : 0;
            __syncthreads();
            sh[tid] += t;
            __syncthreads();
        }
        int incl = sh[tid];
        int c = carry;
        if (i < n) {
            rowptr[i + 1] = c + incl;
            cursor[i]     = c + incl - v;   // exclusive prefix
        }
        __syncthreads();
        if (tid == 1023) carry = c + sh[1023];
        __syncthreads();
    }
}

__global__ void place_edges_kernel(const int* __restrict__ src, const int* __restrict__ dst,
                                   const int* __restrict__ etype, int* __restrict__ cursor,
                                   int* __restrict__ edges) {
    int e = blockIdx.x * blockDim.x + threadIdx.x;
    if (e >= NE) return;
    int d = dst[e];
    int pos = atomicAdd(&cursor[d], 1);
    edges[pos] = src[e] | (etype[e] << 24);
}

// graph_id is sorted: goff[g] = lower_bound(graph_id, g)
__global__ void goff_kernel(const int* __restrict__ graph_id, int* __restrict__ goff) {
    int g = threadIdx.x;
    if (g > NG) return;
    if (g == NG) { goff[NG] = NN; return; }
    int lo = 0, hi = NN;
    while (lo < hi) {
        int mid = (lo + hi) >> 1;
        if (graph_id[mid] < g) lo = mid + 1; else hi = mid;
    }
    goff[g] = lo;
}

__global__ void embed_kernel(const int* __restrict__ text_idx, const float* __restrict__ emb,
                             float* __restrict__ h) {
    int idx = blockIdx.x * blockDim.x + threadIdx.x;
    if (idx >= NN * HD) return;
    int n = idx >> 7, c = idx & 127;
    h[idx] = emb[(size_t)text_idx[n] * HD + c];
}

// segment mean by graph (contiguous node ranges); writes agg[g][slot*128 + c]
__global__ void mean_kernel(const float* __restrict__ h, const int* __restrict__ goff,
                            float* __restrict__ agg, int slot) {
    int g = blockIdx.x;
    int c = threadIdx.x; // 128
    int s = goff[g], e = goff[g + 1];
    float a0 = 0.f, a1 = 0.f, a2 = 0.f, a3 = 0.f;
    int r = s;
    for (; r + 4 <= e; r += 4) {
        a0 += h[(size_t)(r + 0) * HD + c];
        a1 += h[(size_t)(r + 1) * HD + c];
        a2 += h[(size_t)(r + 2) * HD + c];
        a3 += h[(size_t)(r + 3) * HD + c];
    }
    for (; r < e; ++r) a0 += h[(size_t)r * HD + c];
    float acc = (a0 + a1) + (a2 + a3);
    float cntf = (float)((e - s) > 0 ? (e - s) : 1);
    agg[g * K3 + slot * HD + c] = acc / cntf;
}

__device__ __forceinline__ void f4add(float4& a, const float4& b) {
    a.x += b.x; a.y += b.y; a.z += b.z; a.w += b.w;
}

// one warp per dst node: per-etype raw-feature sums -> S[n][t*128 + col], deg counts
__global__ void aggregate_kernel(const float* __restrict__ h, const int* __restrict__ rowptr,
                                 const int* __restrict__ edges, float* __restrict__ S,
                                 float* __restrict__ deg) {
    int warp = (blockIdx.x * blockDim.x + threadIdx.x) >> 5;
    int lane = threadIdx.x & 31;
    if (warp >= NN) return;
    int s = rowptr[warp], e = rowptr[warp + 1];
    float4 a0 = {0,0,0,0}, a1 = {0,0,0,0}, a2 = {0,0,0,0};
    int c0 = 0, c1 = 0, c2 = 0;
    const float4* h4 = (const float4*)h;
    for (int i = s; i < e; ++i) {
        int p = edges[i];
        int srcn = p & 0xFFFFFF;
        int t = p >> 24;
        float4 v = h4[(size_t)srcn * 32 + lane];
        if (t == 0)      { f4add(a0, v); c0++; }
        else if (t == 1) { f4add(a1, v); c1++; }
        else             { f4add(a2, v); c2++; }
    }
    float4* S4 = (float4*)S;
    size_t base = (size_t)warp * 96;
    S4[base + lane]      = a0;
    S4[base + 32 + lane] = a1;
    S4[base + 64 + lane] = a2;
    if (lane == 0) {
        deg[(size_t)warp * 3 + 0] = (float)c0;
        deg[(size_t)warp * 3 + 1] = (float)c1;
        deg[(size_t)warp * 3 + 2] = (float)c2;
    }
}

// ---------------- TF32 tensor-core GEMM: C[m][j] = sum_k A[m][k]*B[j][k] (C = A·B^T) ----
// A: [M x K] row-major (K mult of 32), B: [J x K] row-major (J mult of 128)
// mode 1: +bias[j]; mode 2: +deg[m][t]*bl3[t*128 + (j - j0)]  (J==128 use)
// Block tile 128x128, BK=32, 256 threads = 8 warps, warp tile 64x32 (4x4 m16n8k8 mmas).
// smem: double-buffered A,B tiles [128][36] fp32 (stride 36 -> conflict-free frag reads).
#define GEMM_SMEM_BYTES (2 * 128 * 36 * 2 * 4)

__device__ __forceinline__ unsigned cvt_tf32(float x) {
    unsigned r;
    asm("cvt.rna.tf32.f32 %0, %1;" : "=r"(r) : "f"(x));
    return r;
}

__global__ __launch_bounds__(256) void tf32gemm_abt_kernel(
    const float* __restrict__ A, const float* __restrict__ B, float* __restrict__ C,
    int M, int K, int J, int mode,
    const float* __restrict__ bias, const float* __restrict__ deg,
    const float* __restrict__ bl3)
{
    extern __shared__ unsigned sm[];
    unsigned* AsBase = sm;              // 2 x 128 x 36
    unsigned* BsBase = sm + 2 * 128 * 36;

    const int tid  = threadIdx.x;
    const int warp = tid >> 5;
    const int lane = tid & 31;
    const int g    = lane >> 2;   // 0..7
    const int tg   = lane & 3;    // 0..3
    const int wm   = (warp >> 2) * 64;   // 0 / 64
    const int wn   = (warp & 3) * 32;    // 0..96
    const int m0   = blockIdx.x * 128;
    const int j0   = blockIdx.y * 128;

    float acc[4][4][4];
#pragma unroll
    for (int mi = 0; mi < 4; ++mi)
#pragma unroll
        for (int ni = 0; ni < 4; ++ni)
#pragma unroll
            for (int q = 0; q < 4; ++q) acc[mi][ni][q] = 0.f;

    float4 rA[4], rB[4];
    const int numT = K >> 5;

    auto GLOAD = [&](int t) {
        int k0 = t << 5;
#pragma unroll
        for (int u = 0; u < 4; ++u) {
            int f  = tid + u * 256;
            int r  = f >> 3;
            int kq = (f & 7) << 2;
            int gm = m0 + r;
            rA[u] = (gm < M) ? *(const float4*)(A + (size_t)gm * K + k0 + kq)
                             : make_float4(0.f, 0.f, 0.f, 0.f);
            rB[u] = *(const float4*)(B + (size_t)(j0 + r) * K + k0 + kq);
        }
    };
    auto SSTORE = [&](int buf) {
        unsigned* a = AsBase + buf * (128 * 36);
        unsigned* b = BsBase + buf * (128 * 36);
#pragma unroll
        for (int u = 0; u < 4; ++u) {
            int f  = tid + u * 256;
            int r  = f >> 3;
            int kq = (f & 7) << 2;
            a[r * 36 + kq + 0] = cvt_tf32(rA[u].x);
            a[r * 36 + kq + 1] = cvt_tf32(rA[u].y);
            a[r * 36 + kq + 2] = cvt_tf32(rA[u].z);
            a[r * 36 + kq + 3] = cvt_tf32(rA[u].w);
            b[r * 36 + kq + 0] = cvt_tf32(rB[u].x);
            b[r * 36 + kq + 1] = cvt_tf32(rB[u].y);
            b[r * 36 + kq + 2] = cvt_tf32(rB[u].z);
            b[r * 36 + kq + 3] = cvt_tf32(rB[u].w);
        }
    };
    auto COMP = [&](int buf) {
        const unsigned* a = AsBase + buf * (128 * 36);
        const unsigned* b = BsBase + buf * (128 * 36);
#pragma unroll
        for (int kk = 0; kk < 32; kk += 8) {
            unsigned af[4][4], bf[4][2];
#pragma unroll
            for (int mi = 0; mi < 4; ++mi) {
                int r = wm + mi * 16 + g;
                af[mi][0] = a[r * 36 + kk + tg];
                af[mi][1] = a[(r + 8) * 36 + kk + tg];
                af[mi][2] = a[r * 36 + kk + tg + 4];
                af[mi][3] = a[(r + 8) * 36 + kk + tg + 4];
            }
#pragma unroll
            for (int ni = 0; ni < 4; ++ni) {
                int c = wn + ni * 8 + g;
                bf[ni][0] = b[c * 36 + kk + tg];
                bf[ni][1] = b[c * 36 + kk + tg + 4];
            }
#pragma unroll
            for (int mi = 0; mi < 4; ++mi)
#pragma unroll
                for (int ni = 0; ni < 4; ++ni) {
                    asm volatile(
                        "mma.sync.aligned.m16n8k8.row.col.f32.tf32.tf32.f32 "
                        "{%0,%1,%2,%3}, {%4,%5,%6,%7}, {%8,%9}, {%0,%1,%2,%3};"
                        : "+f"(acc[mi][ni][0]), "+f"(acc[mi][ni][1]),
                          "+f"(acc[mi][ni][2]), "+f"(acc[mi][ni][3])
                        : "r"(af[mi][0]), "r"(af[mi][1]), "r"(af[mi][2]), "r"(af[mi][3]),
                          "r"(bf[ni][0]), "r"(bf[ni][1]));
                }
        }
    };

    GLOAD(0); SSTORE(0); __syncthreads();
    for (int t = 0; t < numT; ++t) {
        if (t + 1 < numT) GLOAD(t + 1);
        COMP(t & 1);
        if (t + 1 < numT) SSTORE((t + 1) & 1);
        __syncthreads();
    }

    // epilogue
#pragma unroll
    for (int mi = 0; mi < 4; ++mi) {
        int r0 = m0 + wm + mi * 16 + g;
        int r1 = r0 + 8;
        float d00 = 0.f, d01 = 0.f, d02 = 0.f, d10 = 0.f, d11 = 0.f, d12 = 0.f;
        if (mode == 2) {
            if (r0 < M) { d00 = deg[(size_t)r0 * 3]; d01 = deg[(size_t)r0 * 3 + 1]; d02 = deg[(size_t)r0 * 3 + 2]; }
            if (r1 < M) { d10 = deg[(size_t)r1 * 3]; d11 = deg[(size_t)r1 * 3 + 1]; d12 = deg[(size_t)r1 * 3 + 2]; }
        }
#pragma unroll
        for (int ni = 0; ni < 4; ++ni) {
            int cl = wn + ni * 8 + tg * 2;    // 0..127 within tile
            int c  = j0 + cl;
            float v00 = acc[mi][ni][0], v01 = acc[mi][ni][1];
            float v10 = acc[mi][ni][2], v11 = acc[mi][ni][3];
            if (mode == 1) {
                float bb0 = bias[c], bb1 = bias[c + 1];
                v00 += bb0; v01 += bb1; v10 += bb0; v11 += bb1;
            } else if (mode == 2) {
                float e00 = bl3[cl],       e01 = bl3[cl + 1];
                float e10 = bl3[128 + cl], e11 = bl3[129 + cl];
                float e20 = bl3[256 + cl], e21 = bl3[257 + cl];
                v00 += d00 * e00 + d01 * e10 + d02 * e20;
                v01 += d00 * e01 + d01 * e11 + d02 * e21;
                v10 += d10 * e00 + d11 * e10 + d12 * e20;
                v11 += d10 * e01 + d11 * e11 + d12 * e21;
            }
            if (r0 < M) *(float2*)(C + (size_t)r0 * J + c) = make_float2(v00, v01);
            if (r1 < M) *(float2*)(C + (size_t)r1 * J + c) = make_float2(v10, v11);
        }
    }
}

// ---------------- GRU gates (in-place h update) ----------------
__global__ void gru_gates_kernel(const float* __restrict__ gi, const float* __restrict__ gh,
                                 float* __restrict__ h) {
    int idx = blockIdx.x * blockDim.x + threadIdx.x;
    if (idx >= NN * HD) return;
    int n = idx >> 7, c = idx & 127;
    size_t b = (size_t)n * K3;
    float ir = gi[b + c],       hr = gh[b + c];
    float iz = gi[b + 128 + c], hz = gh[b + 128 + c];
    float in_ = gi[b + 256 + c], hn = gh[b + 256 + c];
    float r = 1.f / (1.f + expf(-(ir + hr)));
    float z = 1.f / (1.f + expf(-(iz + hz)));
    float nc = tanhf(in_ + r * hn);
    h[idx] = (1.f - z) * nc + z * h[idx];
}

// ---------------- head: x = relu(agg@W1+b1); res = x@W2+b2; emit [res | agg] ----------------
__global__ void head_kernel(const float* __restrict__ agg, const float* __restrict__ W1,
                            const float* __restrict__ b1, const float* __restrict__ W2,
                            const float* __restrict__ b2, float* __restrict__ out,
                            int out_size) {
    int g = blockIdx.x;
    int o = threadIdx.x; // 128
    __shared__ float sa[K3];
    __shared__ float sx[HD];
    for (int k = o; k < K3; k += HD) sa[k] = agg[g * K3 + k];
    __syncthreads();
    float acc = b1[o];
    for (int k = 0; k < K3; ++k) acc += sa[k] * W1[k * HD + o];
    acc = fmaxf(acc, 0.f);
    sx[o] = acc * W2[o];
    __syncthreads();
    for (int st = 64; st > 0; st >>= 1) {
        if (o < st) sx[o] += sx[o + st];
        __syncthreads();
    }
    if (o == 0 && g < out_size) out[g] = sx[0] + b2[0];
    for (int k = o; k < K3; k += HD) {
        int oi = NG + g * K3 + k;
        if (oi < out_size) out[oi] = sa[k];
    }
}

// ---------------- host launch ----------------
extern "C" void kernel_launch(void* const* d_in, const int* in_sizes, int n_in,
                              void* d_out, int out_size) {
    const int*   text_idx = (const int*)d_in[0];
    const int*   src      = (const int*)d_in[1];
    const int*   dst      = (const int*)d_in[2];
    const int*   etype    = (const int*)d_in[3];
    const int*   graph_id = (const int*)d_in[4];
    const float* emb      = (const float*)d_in[5];
    const float* Wl       = (const float*)d_in[6];
    const float* bl       = (const float*)d_in[7];
    const float* W_ih     = (const float*)d_in[8];
    const float* W_hh     = (const float*)d_in[9];
    const float* b_ih     = (const float*)d_in[10];
    const float* b_hh     = (const float*)d_in[11];
    const float* W1       = (const float*)d_in[12];
    const float* b1       = (const float*)d_in[13];
    const float* W2       = (const float*)d_in[14];
    const float* b2       = (const float*)d_in[15];
    float* out = (float*)d_out;

    float *h, *S, *a, *gi, *gh, *deg, *wcatT, *agg;
    int *cnt, *rowptr, *cursor, *edges, *goff;
    cudaGetSymbolAddress((void**)&h,      d_h);
    cudaGetSymbolAddress((void**)&S,      d_S);
    cudaGetSymbolAddress((void**)&a,      d_a);
    cudaGetSymbolAddress((void**)&gi,     d_gi);
    cudaGetSymbolAddress((void**)&gh,     d_gh);
    cudaGetSymbolAddress((void**)&deg,    d_deg);
    cudaGetSymbolAddress((void**)&wcatT,  d_wcatT);
    cudaGetSymbolAddress((void**)&agg,    d_agg);
    cudaGetSymbolAddress((void**)&cnt,    d_cnt);
    cudaGetSymbolAddress((void**)&rowptr, d_rowptr);
    cudaGetSymbolAddress((void**)&cursor, d_cursor);
    cudaGetSymbolAddress((void**)&edges,  d_edges);
    cudaGetSymbolAddress((void**)&goff,   d_goff);

    static bool attr_set = false;
    if (!attr_set) {
        cudaFuncSetAttribute(tf32gemm_abt_kernel,
                             cudaFuncAttributeMaxDynamicSharedMemorySize, GEMM_SMEM_BYTES);
        attr_set = true;
    }

    // one-time (per launch) graph structure + weight transpose
    transpose_wl_kernel<<<(2 * 3 * 128 * 128 + 255) / 256, 256>>>(Wl, wcatT);
    cudaMemsetAsync(cnt, 0, NN * sizeof(int));
    count_edges_kernel<<<(NE + 255) / 256, 256>>>(dst, cnt);
    scan_counts_kernel<<<1, 1024>>>(cnt, rowptr, cursor, NN);
    place_edges_kernel<<<(NE + 255) / 256, 256>>>(src, dst, etype, cursor, edges);
    goff_kernel<<<1, NG + 1>>>(graph_id, goff);

    embed_kernel<<<(NN * HD + 255) / 256, 256>>>(text_idx, emb, h);
    mean_kernel<<<NG, HD>>>(h, goff, agg, 0);

    const dim3 g128((NN + 127) / 128, 1);
    const dim3 g384((NN + 127) / 128, 3);

    for (int l = 0; l < NLAYERS; ++l) {
        for (int s = 0; s < NSTEPS; ++s) {
            aggregate_kernel<<<(NN * 32 + 255) / 256, 256>>>(h, rowptr, edges, S, deg);
            // a = S @ WcatT^T + deg-weighted etype bias
            tf32gemm_abt_kernel<<<g128, 256, GEMM_SMEM_BYTES>>>(
                S, wcatT + (size_t)l * HD * K3, a,
                NN, K3, HD, 2, nullptr, deg, bl + l * K3);
            // gi = a @ W_ih^T + b_ih
            tf32gemm_abt_kernel<<<g384, 256, GEMM_SMEM_BYTES>>>(
                a, W_ih + (size_t)l * K3 * HD, gi,
                NN, HD, K3, 1, b_ih + l * K3, nullptr, nullptr);
            // gh = h @ W_hh^T + b_hh
            tf32gemm_abt_kernel<<<g384, 256, GEMM_SMEM_BYTES>>>(
                h, W_hh + (size_t)l * K3 * HD, gh,
                NN, HD, K3, 1, b_hh + l * K3, nullptr, nullptr);
            gru_gates_kernel<<<(NN * HD + 255) / 256, 256>>>(gi, gh, h);
        }
        mean_kernel<<<NG, HD>>>(h, goff, agg, l + 1);
    }

    head_kernel<<<NG, HD>>>(agg, W1, b1, W2, b2, out, out_size);
}